// round 5
// baseline (speedup 1.0000x reference)
#include <cuda_runtime.h>
#include <math.h>

#define BB   8
#define NN   2048
#define DD   256
#define EE   16
#define HH   8
#define CAPC 256
#define NTOK (BB*NN)
#define NBLK 128

// ------------------------- device scratch (no allocs) -------------------------
__device__ int   d_idx1[NTOK];
__device__ int   d_idx2[NTOK];
__device__ float d_g1[NTOK];
__device__ float d_g2[NTOK];
__device__ float d_gates[NBLK*DD];
__device__ float d_bpart[NBLK*32];      // [blk][0..15]=probsum, [16..31]=count
__device__ unsigned g_ctr = 0;
__device__ unsigned g_gen = 0;

// ---------------- software grid barrier (all 128 blocks resident) ----------------
__device__ __forceinline__ void grid_barrier() {
    __threadfence();                       // publish this thread's writes
    __syncthreads();
    if (threadIdx.x == 0) {
        unsigned gen = atomicAdd(&g_gen, 0u);
        unsigned old = atomicAdd(&g_ctr, 1u);
        if (old == NBLK - 1) {
            g_ctr = 0;
            __threadfence();
            atomicAdd(&g_gen, 1u);         // release
        } else {
            while (atomicAdd(&g_gen, 0u) == gen) { __nanosleep(64); }
        }
        __threadfence();
    }
    __syncthreads();
}

// ------------------------- the whole MoE in one kernel -------------------------
__global__ void __launch_bounds__(1024, 1) k_moe(
    const float* __restrict__ x, const float* __restrict__ audio,
    const float* __restrict__ wg, const float* __restrict__ Wq,
    const float* __restrict__ Wkv, const float* __restrict__ Wp,
    const float* __restrict__ bp, float* __restrict__ out, int out_size)
{
    __shared__ float sU[HH][DD];        // q-through-Wkv_k, persists A -> C
    __shared__ float satt[HH][CAPC];
    __shared__ float sY[HH][DD];
    __shared__ float sRed[4][4][DD];
    __shared__ float sq[DD];
    __shared__ float sa[DD];
    __shared__ float sO[DD];
    __shared__ int   s_slots[CAPC];     // slot -> token, persists B -> C
    __shared__ float sprob[EE];
    __shared__ int   scnt[EE];
    __shared__ int   wsum[33];
    __shared__ int   s_base;
    __shared__ int   s_ti1[128], s_ti2[128];
    __shared__ float s_tw1[128], s_tw2[128];
    __shared__ float slloss[128];

    const int blk  = blockIdx.x;
    const int tid  = threadIdx.x;
    const int lane = tid & 31;
    const int warp = tid >> 5;
    const int g    = tid >> 8;          // warp-group 0..3
    const int wtid = tid & 255;
    const int e    = blk >> 3;          // expert for phases A2/B/C
    const int b    = blk & 7;           // batch  for phases A2/B/C

    // =================== Phase A1: gating for tokens [blk*128, +128) ===================
    if (tid < EE) { sprob[tid] = 0.f; scnt[tid] = 0; }
    __syncthreads();
    {
        const int tokenBase = blk*128 + warp*4;
        for (int i = 0; i < 4; i++) {
            int token = tokenBase + i;
            const float4* xr4 = (const float4*)(x + (size_t)token * DD);
            float4 xa = xr4[lane], xb = xr4[lane + 32];
            float p[EE];
#pragma unroll
            for (int ee = 0; ee < EE; ee++) p[ee] = 0.f;
            const float4* wg4 = (const float4*)wg;   // wg[d][e], row = 4 float4
#pragma unroll
            for (int j = 0; j < 4; j++) {
                float xv = (j==0)?xa.x:(j==1)?xa.y:(j==2)?xa.z:xa.w;
                int d = 4*lane + j;
                float4 w0 = wg4[d*4+0], w1 = wg4[d*4+1], w2 = wg4[d*4+2], w3 = wg4[d*4+3];
                p[0]+=xv*w0.x; p[1]+=xv*w0.y; p[2]+=xv*w0.z; p[3]+=xv*w0.w;
                p[4]+=xv*w1.x; p[5]+=xv*w1.y; p[6]+=xv*w1.z; p[7]+=xv*w1.w;
                p[8]+=xv*w2.x; p[9]+=xv*w2.y; p[10]+=xv*w2.z; p[11]+=xv*w2.w;
                p[12]+=xv*w3.x; p[13]+=xv*w3.y; p[14]+=xv*w3.z; p[15]+=xv*w3.w;
            }
#pragma unroll
            for (int j = 0; j < 4; j++) {
                float xv = (j==0)?xb.x:(j==1)?xb.y:(j==2)?xb.z:xb.w;
                int d = 4*(lane+32) + j;
                float4 w0 = wg4[d*4+0], w1 = wg4[d*4+1], w2 = wg4[d*4+2], w3 = wg4[d*4+3];
                p[0]+=xv*w0.x; p[1]+=xv*w0.y; p[2]+=xv*w0.z; p[3]+=xv*w0.w;
                p[4]+=xv*w1.x; p[5]+=xv*w1.y; p[6]+=xv*w1.z; p[7]+=xv*w1.w;
                p[8]+=xv*w2.x; p[9]+=xv*w2.y; p[10]+=xv*w2.z; p[11]+=xv*w2.w;
                p[12]+=xv*w3.x; p[13]+=xv*w3.y; p[14]+=xv*w3.z; p[15]+=xv*w3.w;
            }
#pragma unroll
            for (int ee = 0; ee < EE; ee++) {
#pragma unroll
                for (int off = 16; off > 0; off >>= 1)
                    p[ee] += __shfl_xor_sync(0xffffffffu, p[ee], off);
            }
            // softmax over 16
            float mx = p[0];
#pragma unroll
            for (int ee = 1; ee < EE; ee++) mx = fmaxf(mx, p[ee]);
            float s = 0.f;
#pragma unroll
            for (int ee = 0; ee < EE; ee++) { p[ee] = expf(p[ee] - mx); s += p[ee]; }
            float inv = 1.f / s;
#pragma unroll
            for (int ee = 0; ee < EE; ee++) p[ee] *= inv;
            // top-1 / top-2 (first-max tie break)
            int i1 = 0; float g1v = p[0];
#pragma unroll
            for (int ee = 1; ee < EE; ee++) if (p[ee] > g1v) { g1v = p[ee]; i1 = ee; }
            int i2 = (i1 == 0) ? 1 : 0; float g2v = p[i2];
#pragma unroll
            for (int ee = 0; ee < EE; ee++)
                if (ee != i1 && p[ee] > g2v) { g2v = p[ee]; i2 = ee; }
            float denom = g1v + g2v + 1e-9f;
            if (lane == 0) {
                d_idx1[token] = i1; d_idx2[token] = i2;
                d_g1[token] = g1v / denom; d_g2[token] = g2v / denom;
                atomicAdd(&scnt[i1], 1);
            }
            if (lane < EE) atomicAdd(&sprob[lane], p[lane]);
        }
    }
    __syncthreads();
    if (tid < EE) {
        d_bpart[blk*32 + tid]      = sprob[tid];
        d_bpart[blk*32 + 16 + tid] = (float)scnt[tid];
    }

    // =================== Phase A2: qU for (e,b) -> sU (smem only) ===================
    if (tid < DD) sa[tid] = audio[b*DD + tid];
    __syncthreads();
    const float* Wqe = Wq + (size_t)e*DD*DD;
    {
        float acc = 0.f;
        int d0 = g*64;
#pragma unroll 4
        for (int d = d0; d < d0 + 64; d++) acc += sa[d] * Wqe[d*DD + wtid];
        sRed[g][0][wtid] = acc;
    }
    __syncthreads();
    if (tid < DD)
        sq[tid] = sRed[0][0][tid] + sRed[1][0][tid] + sRed[2][0][tid] + sRed[3][0][tid];
    __syncthreads();
    const float* Wkve = Wkv + (size_t)e*DD*2*DD;
    {
        int h = warp & 7;
        int dbase = (warp >> 3) * 64;
        float qv = sq[h*32 + lane];
#pragma unroll 4
        for (int d = dbase; d < dbase + 64; d++) {
            float v = Wkve[(size_t)d*512 + h*32 + lane] * qv;
#pragma unroll
            for (int off = 16; off > 0; off >>= 1)
                v += __shfl_xor_sync(0xffffffffu, v, off);
            if (lane == 0) sU[h][d] = v;
        }
    }

    grid_barrier();   // all gating done, everywhere

    // =================== Phase B: positions for (e,b) -> s_slots ===================
    if (tid < CAPC) s_slots[tid] = -1;
    {
        int t0 = tid * 2;                                 // 2 tokens/thread
        int2 a = *(const int2*)(d_idx1 + b*NN + t0);
        int2 c = *(const int2*)(d_idx2 + b*NN + t0);
        for (int pass = 0; pass < 2; pass++) {
            int m0 = (pass == 0) ? (a.x == e) : (c.x == e);
            int m1 = (pass == 0) ? (a.y == e) : (c.y == e);
            int cnt = m0 + m1;
            int incl = cnt;
#pragma unroll
            for (int off = 1; off < 32; off <<= 1) {
                int v = __shfl_up_sync(0xffffffffu, incl, off);
                if (lane >= off) incl += v;
            }
            int excl = incl - cnt;
            if (lane == 31) wsum[warp] = incl;
            __syncthreads();
            if (warp == 0) {
                int t = wsum[lane];
                int sc = t;
#pragma unroll
                for (int off = 1; off < 32; off <<= 1) {
                    int v = __shfl_up_sync(0xffffffffu, sc, off);
                    if (lane >= off) sc += v;
                }
                wsum[lane] = sc - t;                      // exclusive
                if (lane == 31 && pass == 0)
                    s_base = (sc < CAPC) ? sc : CAPC;     // m1_count capped
            }
            __syncthreads();
            int base = excl + wsum[warp] + ((pass == 1) ? s_base : 0);
            if (m0) {
                if (base < CAPC) s_slots[base] = t0;
                else { if (pass == 0) d_g1[b*NN + t0] = 0.f; else d_g2[b*NN + t0] = 0.f; }
                base++;
            }
            if (m1) {
                if (base < CAPC) s_slots[base] = t0 + 1;
                else { if (pass == 0) d_g1[b*NN + t0 + 1] = 0.f; else d_g2[b*NN + t0 + 1] = 0.f; }
            }
            __syncthreads();
        }
    }

    // =================== Phase C: attention (slot-centric, all smem) ===================
    // logits: warp handles 8 slots, U from smem
    {
        const float scale = 0.17677669529663687f;    // 32^-0.5
#pragma unroll
        for (int ci = 0; ci < 8; ci++) {
            int c = warp*8 + ci;
            int tok = s_slots[c];
            float part[HH];
            if (tok >= 0) {
                const float4* xr4 = (const float4*)(x + ((size_t)b*NN + tok)*DD);
                float4 xa = xr4[lane], xb = xr4[lane + 32];
#pragma unroll
                for (int h = 0; h < HH; h++) {
                    const float4* u4 = (const float4*)(&sU[h][0]);
                    float4 ua = u4[lane], ub = u4[lane + 32];
                    part[h] = xa.x*ua.x + xa.y*ua.y + xa.z*ua.z + xa.w*ua.w
                            + xb.x*ub.x + xb.y*ub.y + xb.z*ub.z + xb.w*ub.w;
                }
            } else {
#pragma unroll
                for (int h = 0; h < HH; h++) part[h] = 0.f;
            }
#pragma unroll
            for (int h = 0; h < HH; h++) {
                float v = part[h];
#pragma unroll
                for (int off = 16; off > 0; off >>= 1)
                    v += __shfl_xor_sync(0xffffffffu, v, off);
                if (lane == 0) satt[h][c] = (tok >= 0) ? v * scale : 0.f;
            }
        }
    }
    __syncthreads();
    // softmax per head (warps 0..7); empty slots contribute exp(0-mx)
    if (warp < HH) {
        int h = warp;
        float vals[8];
        float mx = -1e30f;
#pragma unroll
        for (int k = 0; k < 8; k++) { vals[k] = satt[h][lane + 32*k]; mx = fmaxf(mx, vals[k]); }
#pragma unroll
        for (int off = 16; off > 0; off >>= 1)
            mx = fmaxf(mx, __shfl_xor_sync(0xffffffffu, mx, off));
        float s = 0.f;
#pragma unroll
        for (int k = 0; k < 8; k++) { vals[k] = expf(vals[k] - mx); s += vals[k]; }
#pragma unroll
        for (int off = 16; off > 0; off >>= 1)
            s += __shfl_xor_sync(0xffffffffu, s, off);
        float inv = 1.f / s;
#pragma unroll
        for (int k = 0; k < 8; k++) satt[h][lane + 32*k] = vals[k] * inv;
    }
    __syncthreads();
    // y[h][d] = sum_c attn[h][c]*Xe[c][d]; group g covers 64 slots
    {
        float yv[HH];
#pragma unroll
        for (int h = 0; h < HH; h++) yv[h] = 0.f;
        int c0 = g*64;
        for (int ci = 0; ci < 64; ci++) {
            int c = c0 + ci;
            int tok = s_slots[c];
            if (tok >= 0) {
                float xv = x[((size_t)b*NN + tok)*DD + wtid];
#pragma unroll
                for (int h = 0; h < HH; h++) yv[h] += satt[h][c] * xv;
            }
        }
#pragma unroll
        for (int r = 0; r < 2; r++) {
            __syncthreads();
#pragma unroll
            for (int hh = 0; hh < 4; hh++) sRed[g][hh][wtid] = yv[r*4 + hh];
            __syncthreads();
            sY[r*4 + g][wtid] = sRed[0][g][wtid] + sRed[1][g][wtid]
                              + sRed[2][g][wtid] + sRed[3][g][wtid];
        }
    }
    __syncthreads();
    // o[j] = sum_d y[h(j)][d]*Wkv_v[e][d][256+j]
    {
        int h = wtid >> 5;
        float acc = 0.f;
        int d0 = g*64;
#pragma unroll 4
        for (int d = d0; d < d0 + 64; d++)
            acc += sY[h][d] * Wkve[(size_t)d*512 + 256 + wtid];
        sRed[g][0][wtid] = acc;
    }
    __syncthreads();
    if (tid < DD)
        sO[tid] = sRed[0][0][tid] + sRed[1][0][tid] + sRed[2][0][tid] + sRed[3][0][tid];
    __syncthreads();
    // gate[d] = sigmoid(sum_j o[j]*Wp[e][j][d] + bp[e][d])
    {
        const float* Wpe = Wp + (size_t)e*DD*DD;
        float acc = 0.f;
        int j0 = g*64;
#pragma unroll 4
        for (int j = j0; j < j0 + 64; j++) acc += sO[j] * Wpe[j*DD + wtid];
        sRed[g][1][wtid] = acc;
    }
    __syncthreads();
    if (tid < DD) {
        float gsum = sRed[0][1][tid] + sRed[1][1][tid] + sRed[2][1][tid] + sRed[3][1][tid]
                   + bp[e*DD + tid];
        d_gates[blk*DD + tid] = 1.f / (1.f + expf(-gsum));
    }

    grid_barrier();   // all gates + capacity-zeroed g's visible

    // =================== Phase D: combine own 128 tokens (+ loss in block 0) ===========
    {
        const int T0 = blk * 128;
        const int bD = T0 >> 11;                       // batch of these tokens
        if (tid < 128) {
            int t = T0 + tid;
            s_ti1[tid] = d_idx1[t]; s_ti2[tid] = d_idx2[t];
            s_tw1[tid] = d_g1[t];   s_tw2[tid] = d_g2[t];
        }
        __syncthreads();
#pragma unroll
        for (int r = 0; r < 8; r++) {
            int flat = r*1024 + tid;                   // 0..8191
            int tl = flat >> 6, q = flat & 63;
            int token = T0 + tl;
            float w1 = s_tw1[tl], w2 = s_tw2[tl];
            const float4* ga4 = (const float4*)(d_gates + (s_ti1[tl]*BB + bD)*DD);
            const float4* gb4 = (const float4*)(d_gates + (s_ti2[tl]*BB + bD)*DD);
            float4 xv = ((const float4*)x)[(size_t)token*64 + q];
            float4 ga = ga4[q], gb = gb4[q];
            float4 o;
            o.x = xv.x * (w1*ga.x + w2*gb.x);
            o.y = xv.y * (w1*ga.y + w2*gb.y);
            o.z = xv.z * (w1*ga.z + w2*gb.z);
            o.w = xv.w * (w1*ga.w + w2*gb.w);
            ((float4*)out)[(size_t)token*64 + q] = o;
        }
    }

    if (blk == 0) {
        if (tid < 128) {
            int b2 = tid >> 4, e2 = tid & 15;
            float P = 0.f, C = 0.f;
            for (int k = 0; k < 16; k++) {
                P += d_bpart[(b2*16 + k)*32 + e2];
                C += d_bpart[(b2*16 + k)*32 + 16 + e2];
            }
            slloss[tid] = P * C;
        }
        __syncthreads();
        if (tid < 64) slloss[tid] += slloss[tid + 64];
        __syncthreads();
        if (tid < 32) {
            float v = slloss[tid] + slloss[tid + 32];
#pragma unroll
            for (int off = 16; off > 0; off >>= 1)
                v += __shfl_xor_sync(0xffffffffu, v, off);
            if (tid == 0 && out_size > NTOK*DD) {
                float coef = (float)(EE*EE) * 0.01f / ((float)NN * (float)NN * (float)(BB*EE));
                out[NTOK*DD] = v * coef;
            }
        }
    }
}

// ------------------------- launch -------------------------
extern "C" void kernel_launch(void* const* d_in, const int* in_sizes, int n_in,
                              void* d_out, int out_size) {
    const float* x     = (const float*)d_in[0];
    const float* audio = (const float*)d_in[1];
    const float* wg    = (const float*)d_in[2];
    const float* Wq    = (const float*)d_in[3];
    const float* Wkv   = (const float*)d_in[4];
    const float* Wp    = (const float*)d_in[5];
    const float* bp    = (const float*)d_in[6];
    float* out = (float*)d_out;

    k_moe<<<NBLK, 1024>>>(x, audio, wg, Wq, Wkv, Wp, bp, out, out_size);
}